// round 1
// baseline (speedup 1.0000x reference)
#include <cuda_runtime.h>

#define N_  256
#define P_  5
#define H_  32
#define B_  256

#define I_BLK 4
#define B_BLK 128
#define JT    64
#define THRESH_ 0.01f

__global__ __launch_bounds__(256, 1)
void pwl_mlp_kernel(const float* __restrict__ x,
                    const float* __restrict__ adj,
                    const float* __restrict__ bp,
                    const float* __restrict__ w_pw,
                    const float* __restrict__ b_pw,
                    const float* __restrict__ W1,
                    const float* __restrict__ b1,
                    const float* __restrict__ W2,
                    const float* __restrict__ b2,
                    float* __restrict__ out)
{
    // eff-folded piecewise weights: ws4 = eff*w[0..3], ws2 = {eff*w[4], eff*b_pw}
    __shared__ float4 ws4[I_BLK][JT];
    __shared__ float2 ws2[I_BLK][JT];
    __shared__ float4 bpA[I_BLK][JT];   // bp[0..3]
    __shared__ float  bpB[I_BLK][JT];   // bp[4]
    __shared__ float  xs[JT][B_BLK + 1];  // transposed x tile: xs[j][b], padded row
    __shared__ float  mW1[I_BLK][H_];
    __shared__ float  mb1[I_BLK][H_];
    __shared__ float  mW2[I_BLK][2*H_];
    __shared__ float  mb2[I_BLK][2];

    const int tid = threadIdx.x;
    const int i0  = blockIdx.x * I_BLK;
    const int B0  = blockIdx.y * B_BLK;

    // ---- stage per-node MLP params for this block's I rows into smem ----
    for (int t = tid; t < I_BLK * H_; t += 256) {
        int li = t / H_, k = t % H_;
        mW1[li][k] = W1[(i0 + li) * H_ + k];
        mb1[li][k] = b1[(i0 + li) * H_ + k];
    }
    for (int t = tid; t < I_BLK * 2 * H_; t += 256) {
        int li = t / (2 * H_), k = t % (2 * H_);
        mW2[li][k] = W2[(i0 + li) * 2 * H_ + k];
    }
    if (tid < I_BLK * 2) {
        mb2[tid >> 1][tid & 1] = b2[(i0 + (tid >> 1)) * 2 + (tid & 1)];
    }

    const int il = tid >> 6;   // 0..3  (local i)
    const int bt = tid & 63;   // 0..63 (this thread handles b = B0+bt and B0+bt+64)
    const int ig = i0 + il;

    float acc0 = 0.f, acc1 = 0.f;

    for (int j0 = 0; j0 < N_; j0 += JT) {
        // ---- load x tile, transposed into xs[j][b] (coalesced float4 global reads) ----
        {
            const int c4 = tid & 15;     // 16 float4 per row of 64 j
            const int rb = tid >> 4;     // 0..15
            #pragma unroll
            for (int it = 0; it < 8; ++it) {
                int r = rb + it * 16;    // 0..127 (local b)
                float4 v = *reinterpret_cast<const float4*>(
                    x + (size_t)(B0 + r) * N_ + j0 + c4 * 4);
                xs[c4 * 4 + 0][r] = v.x;
                xs[c4 * 4 + 1][r] = v.y;
                xs[c4 * 4 + 2][r] = v.z;
                xs[c4 * 4 + 3][r] = v.w;
            }
        }
        // ---- load w_pw / bp tiles, folding eff = masked adjacency.T on the fly ----
        {
            const int li = tid >> 6;
            const int jj = tid & 63;
            const int jg = j0 + jj;
            const int gi = i0 + li;
            float e = adj[(size_t)jg * N_ + gi];           // adjacency[j, i]
            float eff = (e > THRESH_ && gi != jg) ? e : 0.f;
            const float* wp = w_pw + ((size_t)gi * N_ + jg) * P_;
            const float* tp = bp   + ((size_t)gi * N_ + jg) * P_;
            ws4[li][jj] = make_float4(eff * wp[0], eff * wp[1], eff * wp[2], eff * wp[3]);
            ws2[li][jj] = make_float2(eff * wp[4], eff * b_pw[(size_t)gi * N_ + jg]);
            bpA[li][jj] = make_float4(tp[0], tp[1], tp[2], tp[3]);
            bpB[li][jj] = tp[4];
        }
        __syncthreads();

        // ---- main reduction over this j chunk ----
        #pragma unroll 4
        for (int j = 0; j < JT; ++j) {
            float4 w4 = ws4[il][j];
            float2 w2 = ws2[il][j];
            float4 t4 = bpA[il][j];
            float  t1 = bpB[il][j];
            float  x0 = xs[j][bt];
            float  x1 = xs[j][bt + 64];

            acc0 += w2.y;  // eff * b_pw
            acc1 += w2.y;

            acc0 = fmaf(w4.x, fmaxf(x0 - t4.x, 0.f), acc0);
            acc0 = fmaf(w4.y, fmaxf(x0 - t4.y, 0.f), acc0);
            acc0 = fmaf(w4.z, fmaxf(x0 - t4.z, 0.f), acc0);
            acc0 = fmaf(w4.w, fmaxf(x0 - t4.w, 0.f), acc0);
            acc0 = fmaf(w2.x, fmaxf(x0 - t1,   0.f), acc0);

            acc1 = fmaf(w4.x, fmaxf(x1 - t4.x, 0.f), acc1);
            acc1 = fmaf(w4.y, fmaxf(x1 - t4.y, 0.f), acc1);
            acc1 = fmaf(w4.z, fmaxf(x1 - t4.z, 0.f), acc1);
            acc1 = fmaf(w4.w, fmaxf(x1 - t4.w, 0.f), acc1);
            acc1 = fmaf(w2.x, fmaxf(x1 - t1,   0.f), acc1);
        }
        __syncthreads();
    }

    // ---- fused per-node MLP epilogue: Linear(1,H) -> ReLU -> Linear(H,2) ----
    #pragma unroll
    for (int p = 0; p < 2; ++p) {
        float c = p ? acc1 : acc0;
        int b = B0 + bt + p * 64;
        float m = mb2[il][0];
        float s = mb2[il][1];
        #pragma unroll
        for (int k = 0; k < H_; ++k) {
            float h = fmaxf(fmaf(c, mW1[il][k], mb1[il][k]), 0.f);
            m = fmaf(mW2[il][k],      h, m);
            s = fmaf(mW2[il][H_ + k], h, s);
        }
        out[(size_t)b * N_ + ig]            = m;   // means
        out[(size_t)B_ * N_ + b * N_ + ig]  = s;   // log_stds
    }
}

extern "C" void kernel_launch(void* const* d_in, const int* in_sizes, int n_in,
                              void* d_out, int out_size)
{
    const float* x    = (const float*)d_in[0];
    const float* adj  = (const float*)d_in[1];
    const float* bp   = (const float*)d_in[2];
    const float* w_pw = (const float*)d_in[3];
    const float* b_pw = (const float*)d_in[4];
    const float* W1   = (const float*)d_in[5];
    const float* b1   = (const float*)d_in[6];
    const float* W2   = (const float*)d_in[7];
    const float* b2   = (const float*)d_in[8];
    float* out = (float*)d_out;

    dim3 grid(N_ / I_BLK, B_ / B_BLK);   // (64, 2) = 128 blocks
    pwl_mlp_kernel<<<grid, 256>>>(x, adj, bp, w_pw, b_pw, W1, b1, W2, b2, out);
}